// round 3
// baseline (speedup 1.0000x reference)
#include <cuda_runtime.h>
#include <cstdint>

// Problem constants (fixed by the reference)
#define B_DIM 16
#define S_DIM 4096
#define H_DIM 768
#define NUM_WORDS 2048          // S/2
#define VEC (H_DIM / 4)         // 192 float4 per row
#define WPB 8                   // words per block in main kernel

// Scratch: word start-token table, [B][NUM_WORDS+1].
// Word ids are contiguous 0..maxw (cumsum construction), so every word in that
// range has a boundary token and gets written. starts[b][maxw+1] = S-1 is the
// sentinel (end of last word; token S-1 is SEP=-1). Entries beyond maxw+1 are
// never written and stay zero (device globals are zero-initialized; every call
// performs identical writes, so replays are deterministic). Those give
// s=0,e=0 -> cnt=0 -> output 0, matching the reference for absent words.
__device__ int g_starts[B_DIM * (NUM_WORDS + 1)];

// One thread per token: mark segment starts + write sentinel.
__global__ void scatter_starts_kernel(const int* __restrict__ wid) {
    const int b = blockIdx.y;
    const int t = blockIdx.x * blockDim.x + threadIdx.x;
    const int* row = wid + (size_t)b * S_DIM;
    if (t >= 1 && t < S_DIM - 1) {
        int w = row[t];
        if (w >= 0 && row[t - 1] != w) {
            g_starts[b * (NUM_WORDS + 1) + w] = t;
        }
    } else if (t == S_DIM - 1) {
        int maxw = row[S_DIM - 2];           // last valid word id
        g_starts[b * (NUM_WORDS + 1) + maxw + 1] = S_DIM - 1;
    }
}

// One block per (8 words, batch). Thread c owns float4 column c.
// Phase 1 front-batches 8 independent first-token loads (MLP=8), phase 2
// accumulates leftover tokens, phase 3 scales + stores.
__global__ __launch_bounds__(VEC) void seg_mean_kernel(
    const float4* __restrict__ hs,   // [B, S, VEC]
    float4*       __restrict__ out)  // [B, NUM_WORDS, VEC]
{
    const int b  = blockIdx.y;
    const int w0 = blockIdx.x * WPB;
    const int c  = threadIdx.x;

    __shared__ int sb[WPB + 1];
    if (c <= WPB) sb[c] = g_starts[b * (NUM_WORDS + 1) + w0 + c];
    __syncthreads();

    const float4* __restrict__ base = hs + (size_t)b * S_DIM * VEC;
    float4* __restrict__ ob = out + ((size_t)b * NUM_WORDS + w0) * VEC;

    int s[WPB + 1];
#pragma unroll
    for (int i = 0; i <= WPB; ++i) s[i] = sb[i];

    // Phase 1: first token of each word — 8 independent streaming loads.
    float4 acc[WPB];
#pragma unroll
    for (int i = 0; i < WPB; ++i) {
        acc[i] = __ldcs(base + (size_t)s[i] * VEC + c);
    }

    // Phase 2: remaining tokens (avg ~1 per word).
#pragma unroll
    for (int i = 0; i < WPB; ++i) {
        for (int t = s[i] + 1; t < s[i + 1]; ++t) {
            float4 v = __ldcs(base + (size_t)t * VEC + c);
            acc[i].x += v.x; acc[i].y += v.y; acc[i].z += v.z; acc[i].w += v.w;
        }
    }

    // Phase 3: scale + streaming store. cnt<=0 (absent/sentinel word) -> 0.
#pragma unroll
    for (int i = 0; i < WPB; ++i) {
        const int cnt = s[i + 1] - s[i];
        const float inv = (cnt > 0) ? (1.0f / (float)cnt) : 0.0f;
        float4 r;
        r.x = acc[i].x * inv; r.y = acc[i].y * inv;
        r.z = acc[i].z * inv; r.w = acc[i].w * inv;
        __stcs(ob + (size_t)i * VEC + c, r);
    }
}

extern "C" void kernel_launch(void* const* d_in, const int* in_sizes, int n_in,
                              void* d_out, int out_size)
{
    const float* hs  = (const float*)d_in[0];   // hidden_states [B,S,H] f32
    const int*   wid = (const int*)d_in[1];     // word_ids [B,S] i32
    float*       out = (float*)d_out;           // [B, NUM_WORDS, H] f32

    {
        dim3 grid(S_DIM / 256, B_DIM);
        scatter_starts_kernel<<<grid, 256>>>(wid);
    }
    {
        dim3 grid(NUM_WORDS / WPB, B_DIM);
        seg_mean_kernel<<<grid, VEC>>>((const float4*)hs, (float4*)out);
    }
}

// round 4
// speedup vs baseline: 1.4283x; 1.4283x over previous
#include <cuda_runtime.h>
#include <cstdint>

// Problem constants (fixed by the reference)
#define B_DIM 16
#define S_DIM 4096
#define H_DIM 768
#define NUM_WORDS 2048          // S/2
#define VEC (H_DIM / 4)         // 192 float4 per row
#define W_PB 16                 // words per block in main kernel

// Scratch: word start-token table, [B][NUM_WORDS+1].
// Word ids are contiguous 0..maxw (cumsum construction); starts[b][w] = first
// token of word w; starts[b][maxw+1] = S-1 (sentinel). Entries past maxw+1
// stay 0 (zero-initialized device globals; identical writes every call ->
// deterministic across graph replays). The main kernel monotone-repairs its
// 17-entry window, so stale zeros become empty words (cnt=0 -> zero output),
// matching the reference for absent words.
__device__ int g_starts[B_DIM * (NUM_WORDS + 1)];

// One thread per token: mark segment starts + write sentinel.
__global__ void scatter_starts_kernel(const int* __restrict__ wid) {
    const int b = blockIdx.y;
    const int t = blockIdx.x * blockDim.x + threadIdx.x;
    const int* row = wid + (size_t)b * S_DIM;
    if (t >= 1 && t < S_DIM - 1) {
        int w = row[t];
        if (w >= 0 && row[t - 1] != w) {
            g_starts[b * (NUM_WORDS + 1) + w] = t;
        }
    } else if (t == S_DIM - 1) {
        int maxw = row[S_DIM - 2];           // last valid word id
        g_starts[b * (NUM_WORDS + 1) + maxw + 1] = S_DIM - 1;
    }
}

// One block per (16 words, batch). Thread c owns float4 column c of every row.
// The 16 words cover ONE contiguous token range, so the block does a pure
// sequential stream over input tokens with a single register accumulator that
// flushes at each (block-uniform) word boundary. Depth-2 prefetch ring keeps
// 2 loads in flight per thread; low register count keeps occupancy high.
__global__ __launch_bounds__(VEC) void seg_mean_kernel(
    const float4* __restrict__ hs,   // [B, S, VEC]
    float4*       __restrict__ out)  // [B, NUM_WORDS, VEC]
{
    const int b  = blockIdx.y;
    const int w0 = blockIdx.x * W_PB;
    const int c  = threadIdx.x;

    __shared__ int sm[W_PB + 1];
    if (c <= W_PB) sm[c] = g_starts[b * (NUM_WORDS + 1) + w0 + c];
    __syncthreads();
    // Monotone repair (running max): handles blocks straddling / past maxw.
    if (c == 0) {
        int run = sm[0];
#pragma unroll
        for (int i = 1; i <= W_PB; ++i) {
            run = max(run, sm[i]);
            sm[i] = run;
        }
    }
    __syncthreads();

    const float4* __restrict__ base =
        hs + (size_t)b * S_DIM * VEC + c;
    float4* __restrict__ ob =
        out + ((size_t)b * NUM_WORDS + w0) * VEC + c;

    int t = sm[0];
    const int tEnd = sm[W_PB];
    const int last = tEnd - 1;                // valid when tEnd > t

    float4 v0 = make_float4(0.f, 0.f, 0.f, 0.f);
    float4 v1 = v0;
    if (t < tEnd) {
        v0 = __ldcs(base + (size_t)t * VEC);
        v1 = __ldcs(base + (size_t)min(t + 1, last) * VEC);
    }

    int prev = t;
#pragma unroll 1
    for (int i = 0; i < W_PB; ++i) {
        const int e = sm[i + 1];
        float4 acc = make_float4(0.f, 0.f, 0.f, 0.f);
        while (t < e) {
            float4 cur = v0;
            v0 = v1;
            v1 = __ldcs(base + (size_t)min(t + 2, last) * VEC);
            ++t;
            acc.x += cur.x; acc.y += cur.y;
            acc.z += cur.z; acc.w += cur.w;
        }
        const int cnt = e - prev;
        prev = e;
        const float inv = (cnt > 0) ? (1.0f / (float)cnt) : 0.0f;
        float4 r;
        r.x = acc.x * inv; r.y = acc.y * inv;
        r.z = acc.z * inv; r.w = acc.w * inv;
        __stcs(ob + (size_t)i * VEC, r);
    }
}

extern "C" void kernel_launch(void* const* d_in, const int* in_sizes, int n_in,
                              void* d_out, int out_size)
{
    const float* hs  = (const float*)d_in[0];   // hidden_states [B,S,H] f32
    const int*   wid = (const int*)d_in[1];     // word_ids [B,S] i32
    float*       out = (float*)d_out;           // [B, NUM_WORDS, H] f32

    {
        dim3 grid(S_DIM / 256, B_DIM);
        scatter_starts_kernel<<<grid, 256>>>(wid);
    }
    {
        dim3 grid(NUM_WORDS / W_PB, B_DIM);
        seg_mean_kernel<<<grid, VEC>>>((const float4*)hs, (float4*)out);
    }
}